// round 13
// baseline (speedup 1.0000x reference)
#include <cuda_runtime.h>
#include <math.h>
#include <stdint.h>

#define NCELLS 131072
#define HID 128
#define OUTD 64
#define TC 32                 // cells per block
#define NBLK (NCELLS / TC)    // 4096
#define BT 256                // threads per block (8 warps)

#define AP 132                // pitch for H/B1/B2 (mod 32 == 4 -> conflict-free)
#define OP 68                 // pitch for OUT

// ---- dynamic smem layout (float offsets) ----
#define OFF_H    0                        // [32][AP]
#define OFF_B1   (OFF_H + TC * AP)        // [32][AP] relu_a
#define OFF_B2   (OFF_B1 + TC * AP)       // [32][AP] relu_g
#define OFF_OUT  (OFF_B2 + TC * AP)       // [32][OP], col 64 = rna(t)
#define OFF_PART (OFF_OUT + TC * OP)      // [128] faction partials
#define OFF_RED  (OFF_PART + 128)         // esm[32], tsm[32]
#define SMEM_FLOATS (OFF_RED + 64)
#define SMEM_BYTES (SMEM_FLOATS * 4)      // ~60 KB -> L1D carveout ~110 KB

// ---- packed weight image (ks-major: [ks][row][8] per matrix) ----
#define PW_W1  0              // R=256, K=128  ([W1a;W1g] hidden part)
#define PW_W2C 32768          // R=64,  K=256  ([W2a | -W2g])
#define PW_WIH 49152          // R=384, K=64   (rows: ir, iz, i_n)
#define PW_WHH 73728          // R=384, K=128  (rows: hr, hz, hn)
#define WPACK_FLOATS 122880

// ---- scratch (device globals) ----
__device__ float g_wpack[WPACK_FLOATS];
__device__ float g_w64[384];                 // Wih[:,64] (t column)
__device__ float g_newh[NCELLS * HID];
__device__ float g_pfm[NBLK * HID];
__device__ float g_peout[NBLK * OUTD];
__device__ float g_pe[NBLK];
__device__ float g_pt[NBLK];
__device__ float g_v1[256];                  // W1[:, :64]@x + b1 (a then g)
__device__ float g_fm[8 * HID];
__device__ float g_go[HID];

__device__ __forceinline__ float sigmoidf_(float v) {
  return 1.0f / (1.0f + __expf(-v));
}
__device__ __forceinline__ float tanhf_(float v) {
  return 2.0f / (1.0f + __expf(-2.0f * v)) - 1.0f;
}

__device__ __forceinline__ float rna_tf32(float x) {
  uint32_t u;
  asm("cvt.rna.tf32.f32 %0, %1;" : "=r"(u) : "f"(x));
  return __uint_as_float(u);
}

__device__ __forceinline__ void mma_tf32(float* d, const uint32_t* a, uint32_t b0, uint32_t b1) {
  asm volatile(
      "mma.sync.aligned.m16n8k8.row.col.f32.tf32.tf32.f32 "
      "{%0,%1,%2,%3}, {%4,%5,%6,%7}, {%8,%9}, {%0,%1,%2,%3};\n"
      : "+f"(d[0]), "+f"(d[1]), "+f"(d[2]), "+f"(d[3])
      : "r"(a[0]), "r"(a[1]), "r"(a[2]), "r"(a[3]), "r"(b0), "r"(b1));
}

// ============================================================================
// kprep: rna-convert + permute weights into ks-major fragment image.
// (r, k): ks = k/8, q = k%8 -> dst = ks*R*8 + r*8 + p, p = 2q (q<4) else 2(q-4)+1.
// ============================================================================
__global__ void kprep(const float* __restrict__ W1a, const float* __restrict__ W2a,
                      const float* __restrict__ W1g, const float* __restrict__ W2g,
                      const float* __restrict__ Wih, const float* __restrict__ Whh) {
  int seg = blockIdx.y;
  int e = blockIdx.x * 256 + threadIdx.x;
  int R, K, dstoff;
  if (seg == 0)      { R = 256; K = 128; dstoff = PW_W1; }
  else if (seg == 1) { R = 64;  K = 256; dstoff = PW_W2C; }
  else if (seg == 2) { R = 384; K = 64;  dstoff = PW_WIH; }
  else if (seg == 3) { R = 384; K = 128; dstoff = PW_WHH; }
  else {             // Wih col 64
    if (e < 384) g_w64[e] = rna_tf32(Wih[e * 65 + 64]);
    return;
  }
  if (e >= R * K) return;
  int r = e / K, pcol = e - r * K;
  int ks = pcol >> 3, p8 = pcol & 7;
  int k = ks * 8 + (p8 >> 1) + ((p8 & 1) << 2);
  float v;
  if (seg == 0) {
    v = (r < 128) ? rna_tf32(W1a[r * 192 + 64 + k]) : rna_tf32(W1g[(r - 128) * 192 + 64 + k]);
  } else if (seg == 1) {
    v = (k < 128) ? rna_tf32(W2a[r * 128 + k]) : -rna_tf32(W2g[r * 128 + k - 128]);
  } else if (seg == 2) {
    v = rna_tf32(Wih[r * 65 + k]);
  } else {
    v = rna_tf32(Whh[r * 128 + k]);
  }
  g_wpack[dstoff + ks * R * 8 + r * 8 + p8] = v;
}

// ============================================================================
// k0: v1a/v1g = W1[:, :64] @ x + b1 (fp32 exact)
// ============================================================================
__global__ void k0(const float* __restrict__ x,
                   const float* __restrict__ W1a, const float* __restrict__ b1a,
                   const float* __restrict__ W1g, const float* __restrict__ b1g) {
  __shared__ float xs[64];
  int t = threadIdx.x;
  if (t < 64) xs[t] = x[t];
  __syncthreads();
  const float* W = (t < 128) ? W1a : W1g;
  const float* b = (t < 128) ? b1a : b1g;
  int n = t & 127;
  float s = b[n];
#pragma unroll 8
  for (int k = 0; k < 64; k++) s = fmaf(W[n * 192 + k], xs[k], s);
  g_v1[t] = s;
}

// kdummy: placeholder so ncu's fixed capture index lands on k1.
__global__ void kdummy() {}

// ============================================================================
// mma core: MT m-tiles (16 cells each, from moff), NT n-tiles, 1-deep A/B
// software pipeline. RS = per-ks float stride in the ks-major weight image.
// CAT: A = [buf1 | buf2] along K (K8 total chunks, half each).
// ============================================================================
template <int K8, int NT, int RS, bool CAT, int MT>
__device__ __forceinline__ void mma_core(
    const float* sm, int abase, int apitch, int abase2, int moff,
    const float* const (&wp)[NT],
    int g, int tq, float (&d)[MT][NT][4]) {
  uint32_t a[MT][4];
  float2 bf[NT];
  {
    const float* apb = sm + abase + (moff + g) * apitch + tq;
#pragma unroll
    for (int mt = 0; mt < MT; mt++) {
      const float* ap = apb + mt * 16 * apitch;
      a[mt][0] = __float_as_uint(ap[0]);
      a[mt][1] = __float_as_uint(ap[8 * apitch]);
      a[mt][2] = __float_as_uint(ap[4]);
      a[mt][3] = __float_as_uint(ap[8 * apitch + 4]);
    }
#pragma unroll
    for (int nt = 0; nt < NT; nt++) bf[nt] = *(const float2*)(wp[nt]);
  }
#pragma unroll
  for (int ks = 0; ks < K8; ks++) {
    uint32_t an[MT][4];
    float2 bn[NT];
    if (ks + 1 < K8) {
      int ab = abase, kk = ks + 1;
      if (CAT) { if (kk >= K8 / 2) { ab = abase2; kk -= K8 / 2; } }
      const float* apb = sm + ab + (moff + g) * apitch + kk * 8 + tq;
#pragma unroll
      for (int mt = 0; mt < MT; mt++) {
        const float* ap = apb + mt * 16 * apitch;
        an[mt][0] = __float_as_uint(ap[0]);
        an[mt][1] = __float_as_uint(ap[8 * apitch]);
        an[mt][2] = __float_as_uint(ap[4]);
        an[mt][3] = __float_as_uint(ap[8 * apitch + 4]);
      }
#pragma unroll
      for (int nt = 0; nt < NT; nt++)
        bn[nt] = *(const float2*)(wp[nt] + (size_t)(ks + 1) * RS);
    }
#pragma unroll
    for (int nt = 0; nt < NT; nt++) {
      uint32_t b0 = __float_as_uint(bf[nt].x), b1 = __float_as_uint(bf[nt].y);
#pragma unroll
      for (int mt = 0; mt < MT; mt++) mma_tf32(d[mt][nt], a[mt], b0, b1);
    }
    if (ks + 1 < K8) {
#pragma unroll
      for (int nt = 0; nt < NT; nt++) bf[nt] = bn[nt];
#pragma unroll
      for (int mt = 0; mt < MT; mt++)
#pragma unroll
        for (int i = 0; i < 4; i++) a[mt][i] = an[mt][i];
    }
  }
}

template <int MT, int NT>
__device__ __forceinline__ void dzero(float (&d)[MT][NT][4]) {
#pragma unroll
  for (int mt = 0; mt < MT; mt++)
#pragma unroll
    for (int nt = 0; nt < NT; nt++)
#pragma unroll
      for (int i = 0; i < 4; i++) d[mt][nt][i] = 0.0f;
}

// ============================================================================
// K1: fused engines + tension + GRU. 32 cells/block, 8 warps, 2 CTAs/SM.
// 3 GEMM stages: G1a (engines), T3 (out), fused Whh+Wih+GRU.
// ============================================================================
__global__ void __launch_bounds__(BT, 2) k1(
    const float* __restrict__ hiddens,
    const float* __restrict__ b2a, const float* __restrict__ b2g,
    const float* __restrict__ bih, const float* __restrict__ bhh) {
  extern __shared__ float sm[];
  const int t = threadIdx.x;
  const int cell0 = blockIdx.x * TC;
  const int lane = t & 31, wn = t >> 5;
  const int g = lane >> 2, tq = lane & 3;

  if (t < 128) sm[OFF_PART + t] = 0.0f;

  // stage h (rna tf32): [32 cells][128] at pitch AP
  const float4* hsrc = (const float4*)(hiddens + (size_t)cell0 * HID);
  for (int i = t; i < TC * 32; i += BT) {
    int c = i >> 5, q = i & 31;
    float4 v = hsrc[i];
    v.x = rna_tf32(v.x); v.y = rna_tf32(v.y); v.z = rna_tf32(v.z); v.w = rna_tf32(v.w);
    *(float4*)&sm[OFF_H + c * AP + 4 * q] = v;
  }

  // ---------------- G1a: [relu_a | relu_g] = relu(H @ [W1a;W1g]^T + v1) ------
  {
    __syncthreads();
    float d[2][4][4]; dzero<2, 4>(d);
    const int nb = wn * 32;                 // n in 0..255
    const float* wp[4];
#pragma unroll
    for (int nt = 0; nt < 4; nt++)
      wp[nt] = g_wpack + PW_W1 + (size_t)(nb + nt * 8 + g) * 8 + 2 * tq;
    mma_core<16, 4, 2048, false, 2>(sm, OFF_H, AP, 0, 0, wp, g, tq, d);
#pragma unroll
    for (int nt = 0; nt < 4; nt++) {
      int n = nb + nt * 8 + 2 * tq;
      int base = (n < 128) ? OFF_B1 : OFF_B2;
      int nc = n & 127;
      float bv0 = g_v1[n], bv1 = g_v1[n + 1];
#pragma unroll
      for (int mt = 0; mt < 2; mt++)
#pragma unroll
        for (int rh = 0; rh < 2; rh++) {
          int c = mt * 16 + g + rh * 8;
          sm[base + c * AP + nc]     = rna_tf32(fmaxf(d[mt][nt][rh * 2] + bv0, 0.0f));
          sm[base + c * AP + nc + 1] = rna_tf32(fmaxf(d[mt][nt][rh * 2 + 1] + bv1, 0.0f));
        }
    }
  }

  // ---------------- T3: OUT = [B1|B2] @ [W2a|-W2g]^T + (b2a-b2g) (fp32) ------
  {
    __syncthreads();
    float d[2][1][4]; dzero<2, 1>(d);
    const int nb = wn * 8;                  // n in 0..63
    const float* wp[1];
    wp[0] = g_wpack + PW_W2C + (size_t)(nb + g) * 8 + 2 * tq;
    mma_core<32, 1, 512, true, 2>(sm, OFF_B1, AP, OFF_B2, 0, wp, g, tq, d);
    {
      int n = nb + 2 * tq;
      float bv0 = b2a[n] - b2g[n], bv1 = b2a[n + 1] - b2g[n + 1];
#pragma unroll
      for (int mt = 0; mt < 2; mt++)
#pragma unroll
        for (int rh = 0; rh < 2; rh++) {
          int c = mt * 16 + g + rh * 8;
          sm[OFF_OUT + c * OP + n]     = d[mt][0][rh * 2] + bv0;
          sm[OFF_OUT + c * OP + n + 1] = d[mt][0][rh * 2 + 1] + bv1;
        }
    }
  }
  __syncthreads();

  // ---------------- tension + softmax/pool partials ----------------
  {
    float* outb = sm + OFF_OUT;
    float* esm = sm + OFF_RED;
    float* tsm = sm + OFF_RED + TC;
    if (t < TC) {
      float s = 0.0f;
#pragma unroll
      for (int n = 0; n < OUTD; n++) { float v = outb[t * OP + n]; s = fmaf(v, v, s); }
      float tc = s * (1.0f / OUTD);
      outb[t * OP + 64] = rna_tf32(tc);
      esm[t] = expf(tc);
      tsm[t] = tc;
    }
    __syncthreads();
    if (t < OUTD) {
      float s = 0.0f;
#pragma unroll
      for (int c = 0; c < TC; c++) s = fmaf(esm[c], outb[c * OP + t], s);
      g_peout[blockIdx.x * OUTD + t] = s;
    }
    if (t == 0) {
      float se = 0.0f, st = 0.0f;
#pragma unroll
      for (int c = 0; c < TC; c++) { se += esm[c]; st += tsm[c]; }
      g_pe[blockIdx.x] = se;
      g_pt[blockIdx.x] = st;
    }
    __syncthreads();
    for (int i = t; i < TC * OUTD; i += BT) {
      int c = i >> 6, n = i & 63;
      outb[c * OP + n] = rna_tf32(outb[c * OP + n]);
    }
    __syncthreads();
  }

  // ---------------- Fused Whh + Wih + GRU epilogue ----------------
  // Row ownership (both gemms): row = gate*128 + wn*16 + j*8, nt = gate*2 + j.
  // hh accumulators (raw, no bias) stay in registers; i-gemm runs per m-half.
  {
    const int nb16 = wn * 16;               // hidden col group 0..127
    const float* wph[6];
    const float* wpi[6];
#pragma unroll
    for (int nt = 0; nt < 6; nt++) {
      int row = (nt >> 1) * 128 + nb16 + ((nt & 1) << 3) + g;
      wph[nt] = g_wpack + PW_WHH + (size_t)row * 8 + 2 * tq;
      wpi[nt] = g_wpack + PW_WIH + (size_t)row * 8 + 2 * tq;
    }
    float dh[2][6][4]; dzero<2, 6>(dh);
    mma_core<16, 6, 3072, false, 2>(sm, OFF_H, AP, 0, 0, wph, g, tq, dh);

    // biases / t-column weights (per j)
    float bir[2][2], biz[2][2], bin[2][2], wr[2][2], wz[2][2], wnn[2][2];
    float bhr[2][2], bhz[2][2], bhn[2][2];
#pragma unroll
    for (int j = 0; j < 2; j++) {
      int n = nb16 + j * 8 + 2 * tq;
      bir[j][0] = bih[n];        bir[j][1] = bih[n + 1];
      biz[j][0] = bih[128 + n];  biz[j][1] = bih[128 + n + 1];
      bin[j][0] = bih[256 + n];  bin[j][1] = bih[256 + n + 1];
      wr[j][0] = g_w64[n];       wr[j][1] = g_w64[n + 1];
      wz[j][0] = g_w64[128 + n]; wz[j][1] = g_w64[128 + n + 1];
      wnn[j][0] = g_w64[256 + n]; wnn[j][1] = g_w64[256 + n + 1];
      bhr[j][0] = bhh[n];        bhr[j][1] = bhh[n + 1];
      bhz[j][0] = bhh[128 + n];  bhz[j][1] = bhh[128 + n + 1];
      bhn[j][0] = bhh[256 + n];  bhn[j][1] = bhh[256 + n + 1];
    }

#pragma unroll
    for (int mh = 0; mh < 2; mh++) {
      float di[1][6][4]; dzero<1, 6>(di);
      mma_core<8, 6, 3072, false, 1>(sm, OFF_OUT, OP, 0, mh * 16, wpi, g, tq, di);
#pragma unroll
      for (int j = 0; j < 2; j++) {
        int n = nb16 + j * 8 + 2 * tq;
        float p0 = 0.0f, p1 = 0.0f;
#pragma unroll
        for (int rh = 0; rh < 2; rh++) {
          int c = mh * 16 + g + rh * 8;
          float tc = sm[OFF_OUT + c * OP + 64];
          float ir0 = di[0][j][rh * 2]         + bir[j][0] + tc * wr[j][0];
          float ir1 = di[0][j][rh * 2 + 1]     + bir[j][1] + tc * wr[j][1];
          float iz0 = di[0][2 + j][rh * 2]     + biz[j][0] + tc * wz[j][0];
          float iz1 = di[0][2 + j][rh * 2 + 1] + biz[j][1] + tc * wz[j][1];
          float in0 = di[0][4 + j][rh * 2]     + bin[j][0] + tc * wnn[j][0];
          float in1 = di[0][4 + j][rh * 2 + 1] + bin[j][1] + tc * wnn[j][1];
          float hr0 = dh[mh][j][rh * 2],         hr1 = dh[mh][j][rh * 2 + 1];
          float hz0 = dh[mh][2 + j][rh * 2],     hz1 = dh[mh][2 + j][rh * 2 + 1];
          float hn0 = dh[mh][4 + j][rh * 2],     hn1 = dh[mh][4 + j][rh * 2 + 1];
          float2 h = *(const float2*)&sm[OFF_H + c * AP + n];
          float r0 = sigmoidf_(ir0 + hr0 + bhr[j][0]);
          float r1 = sigmoidf_(ir1 + hr1 + bhr[j][1]);
          float z0 = sigmoidf_(iz0 + hz0 + bhz[j][0]);
          float z1 = sigmoidf_(iz1 + hz1 + bhz[j][1]);
          float nv0 = tanhf_(in0 + r0 * (hn0 + bhn[j][0]));
          float nv1 = tanhf_(in1 + r1 * (hn1 + bhn[j][1]));
          float nh0 = (1.0f - z0) * nv0 + z0 * h.x;
          float nh1 = (1.0f - z1) * nv1 + z1 * h.y;
          *(float2*)(g_newh + (size_t)(cell0 + c) * HID + n) = make_float2(nh0, nh1);
          p0 += nh0; p1 += nh1;
        }
        atomicAdd(&sm[OFF_PART + n], p0);
        atomicAdd(&sm[OFF_PART + n + 1], p1);
      }
    }
  }
  __syncthreads();
  if (t < 128) g_pfm[blockIdx.x * HID + t] = sm[OFF_PART + t];
}

// ============================================================================
// K2a: faction means (parallel, coalesced). 512 blocks per faction.
// ============================================================================
__global__ void __launch_bounds__(128) k2a() {
  int f = blockIdx.x, d = threadIdx.x;
  const float* p = g_pfm + (size_t)f * 512 * HID + d;
  float s = 0.0f;
#pragma unroll 16
  for (int b = 0; b < 512; b++) s += p[b * HID];
  g_fm[f * HID + d] = s * (1.0f / 16384.0f);
}

// ============================================================================
// K2b: global opinion, scalar reductions, pooled head
// ============================================================================
__global__ void __launch_bounds__(256) k2b(const float* __restrict__ Wo,
                                           const float* __restrict__ bo,
                                           float* __restrict__ d_out) {
  __shared__ float red[256];
  __shared__ float pout[4][64];
  __shared__ float comb[64];
  __shared__ float sume_s;
  int t = threadIdx.x;

  if (t < HID) {
    float s = 0.0f;
#pragma unroll
    for (int f = 0; f < 8; f++) s += g_fm[f * HID + t];
    g_go[t] = s * 0.125f;
  }

  {
    int o = t & 63, j = t >> 6;
    const float* p = g_peout + (size_t)j * 1024 * 64 + o;
    float s = 0.0f;
#pragma unroll 16
    for (int b = 0; b < 1024; b++) s += p[b * 64];
    pout[j][o] = s;
  }

  float se = 0.0f, st = 0.0f;
  for (int b = t; b < NBLK; b += 256) { se += g_pe[b]; st += g_pt[b]; }
  red[t] = se;
  __syncthreads();
  for (int s2 = 128; s2 > 0; s2 >>= 1) { if (t < s2) red[t] += red[t + s2]; __syncthreads(); }
  if (t == 0) sume_s = red[0];
  __syncthreads();
  red[t] = st;
  __syncthreads();
  for (int s2 = 128; s2 > 0; s2 >>= 1) { if (t < s2) red[t] += red[t + s2]; __syncthreads(); }
  if (t == 0) d_out[64] = red[0] * (1.0f / NCELLS);

  if (t < 64) comb[t] = (((pout[0][t] + pout[1][t]) + pout[2][t]) + pout[3][t]) / sume_s;
  __syncthreads();
  if (t < 64) {
    float s = bo[t];
#pragma unroll
    for (int d = 0; d < 64; d++) s = fmaf(Wo[t * 64 + d], comb[d], s);
    d_out[t] = s;
  }
}

// ============================================================================
// K3: apply faction sync + debate, stream to output
// ============================================================================
__global__ void __launch_bounds__(256) k3(const int* __restrict__ step,
                                          float* __restrict__ d_out) {
  int i = blockIdx.x * 256 + threadIdx.x;
  float4 nh = ((const float4*)g_newh)[i];
  int c = i >> 5;
  int dq = i & 31;
  int f = c >> 14;
  float4 fm4 = ((const float4*)g_fm)[f * 32 + dq];
  float4 v;
  v.x = 0.85f * nh.x + 0.15f * fm4.x;
  v.y = 0.85f * nh.y + 0.15f * fm4.y;
  v.z = 0.85f * nh.z + 0.15f * fm4.z;
  v.w = 0.85f * nh.w + 0.15f * fm4.w;
  if (((c & 16383) < 4096) && (*step > 5)) {
    float4 go4 = ((const float4*)g_go)[dq];
    v.x = 0.85f * v.x + 0.15f * go4.x;
    v.y = 0.85f * v.y + 0.15f * go4.y;
    v.z = 0.85f * v.z + 0.15f * go4.z;
    v.w = 0.85f * v.w + 0.15f * go4.w;
  }
  float* o = d_out + 65 + (size_t)i * 4;
  o[0] = v.x; o[1] = v.y; o[2] = v.z; o[3] = v.w;
}

extern "C" void kernel_launch(void* const* d_in, const int* in_sizes, int n_in,
                              void* d_out, int out_size) {
  const float* x    = (const float*)d_in[0];
  const float* hid  = (const float*)d_in[1];
  const float* W1a  = (const float*)d_in[2];
  const float* b1a  = (const float*)d_in[3];
  const float* W2a  = (const float*)d_in[4];
  const float* b2a  = (const float*)d_in[5];
  const float* W1g  = (const float*)d_in[6];
  const float* b1g  = (const float*)d_in[7];
  const float* W2g  = (const float*)d_in[8];
  const float* b2g  = (const float*)d_in[9];
  const float* Wih  = (const float*)d_in[10];
  const float* Whh  = (const float*)d_in[11];
  const float* bih  = (const float*)d_in[12];
  const float* bhh  = (const float*)d_in[13];
  const float* Wo   = (const float*)d_in[14];
  const float* bo   = (const float*)d_in[15];
  const int* step   = (const int*)d_in[16];
  float* out = (float*)d_out;

  cudaFuncSetAttribute(k1, cudaFuncAttributeMaxDynamicSharedMemorySize, SMEM_BYTES);

  kprep<<<dim3(192, 5), 256>>>(W1a, W2a, W1g, W2g, Wih, Whh);      // launch 0
  k0<<<1, 256>>>(x, W1a, b1a, W1g, b1g);                           // launch 1
  kdummy<<<1, 32>>>();                                             // launch 2 (capture pad)
  k1<<<NBLK, BT, SMEM_BYTES>>>(hid, b2a, b2g, bih, bhh);           // launch 3 <- ncu
  k2a<<<8, 128>>>();                                               // launch 4
  k2b<<<1, 256>>>(Wo, bo, out);                                    // launch 5
  k3<<<(NCELLS * HID / 4) / 256, 256>>>(step, out);                // launch 6
}

// round 14
// speedup vs baseline: 1.1807x; 1.1807x over previous
#include <cuda_runtime.h>
#include <math.h>
#include <stdint.h>

#define NCELLS 131072
#define HID 128
#define OUTD 64
#define TC 32                 // cells per block
#define NBLK (NCELLS / TC)    // 4096
#define BT 256                // threads per block (8 warps)

#define AP 132                // pitch for H/B1/B2 (mod 32 == 4 -> conflict-free)
#define HRP 388               // pitch for HR raw buffer (mod 32 == 4)
#define OP 68                 // pitch for OUT

// ---- dynamic smem layout (float offsets) ----
#define OFF_H    0                        // [32][AP]
#define OFF_B1   (OFF_H + TC * AP)        // [32][AP] relu_a
#define OFF_B2   (OFF_B1 + TC * AP)       // [32][AP] relu_g
#define OFF_HR   (OFF_B2 + TC * AP)       // [32][HRP] raw hr|hz|hn (no bias)
#define OFF_OUT  (OFF_HR + TC * HRP)      // [32][OP], col 64 = rna(t)
#define OFF_PART (OFF_OUT + TC * OP)      // [128] faction partials
#define OFF_RED  (OFF_PART + 128)         // esm[32], tsm[32]
#define SMEM_FLOATS (OFF_RED + 64)
#define SMEM_BYTES (SMEM_FLOATS * 4)

// ---- packed weight image (ks-major: [ks][row][8] per matrix) ----
#define PW_W1  0              // R=256, K=128  ([W1a;W1g] hidden part)
#define PW_W2C 32768          // R=64,  K=256  ([W2a | -W2g])
#define PW_WIH 49152          // R=384, K=64   (rows: ir, iz, i_n)
#define PW_WHH 73728          // R=384, K=128  (rows: hr, hz, hn)
#define WPACK_FLOATS 122880

// ---- scratch (device globals) ----
__device__ float g_wpack[WPACK_FLOATS];
__device__ float g_w64[384];                 // Wih[:,64] (t column)
__device__ float g_newh[NCELLS * HID];
__device__ float g_pfm[NBLK * HID];
__device__ float g_peout[NBLK * OUTD];
__device__ float g_pout2[64 * 64];           // 2nd-level peout partials
__device__ float g_pe[NBLK];
__device__ float g_pt[NBLK];
__device__ float g_v1[256];                  // W1[:, :64]@x + b1 (a then g)
__device__ float g_fm[8 * HID];
__device__ float g_go[HID];

__device__ __forceinline__ float sigmoidf_(float v) {
  return 1.0f / (1.0f + __expf(-v));
}
__device__ __forceinline__ float tanhf_(float v) {
  return 2.0f / (1.0f + __expf(-2.0f * v)) - 1.0f;
}

__device__ __forceinline__ float rna_tf32(float x) {
  uint32_t u;
  asm("cvt.rna.tf32.f32 %0, %1;" : "=r"(u) : "f"(x));
  return __uint_as_float(u);
}

__device__ __forceinline__ void mma_tf32(float* d, const uint32_t* a, uint32_t b0, uint32_t b1) {
  asm volatile(
      "mma.sync.aligned.m16n8k8.row.col.f32.tf32.tf32.f32 "
      "{%0,%1,%2,%3}, {%4,%5,%6,%7}, {%8,%9}, {%0,%1,%2,%3};\n"
      : "+f"(d[0]), "+f"(d[1]), "+f"(d[2]), "+f"(d[3])
      : "r"(a[0]), "r"(a[1]), "r"(a[2]), "r"(a[3]), "r"(b0), "r"(b1));
}

// ============================================================================
// kprep: rna-convert + permute weights into ks-major fragment image.
// (r, k): ks = k/8, q = k%8 -> dst = ks*R*8 + r*8 + p, p = 2q (q<4) else 2(q-4)+1.
// ============================================================================
__global__ void kprep(const float* __restrict__ W1a, const float* __restrict__ W2a,
                      const float* __restrict__ W1g, const float* __restrict__ W2g,
                      const float* __restrict__ Wih, const float* __restrict__ Whh) {
  int seg = blockIdx.y;
  int e = blockIdx.x * 256 + threadIdx.x;
  int R, K, dstoff;
  if (seg == 0)      { R = 256; K = 128; dstoff = PW_W1; }
  else if (seg == 1) { R = 64;  K = 256; dstoff = PW_W2C; }
  else if (seg == 2) { R = 384; K = 64;  dstoff = PW_WIH; }
  else if (seg == 3) { R = 384; K = 128; dstoff = PW_WHH; }
  else {             // Wih col 64
    if (e < 384) g_w64[e] = rna_tf32(Wih[e * 65 + 64]);
    return;
  }
  if (e >= R * K) return;
  int r = e / K, pcol = e - r * K;
  int ks = pcol >> 3, p8 = pcol & 7;
  int k = ks * 8 + (p8 >> 1) + ((p8 & 1) << 2);
  float v;
  if (seg == 0) {
    v = (r < 128) ? rna_tf32(W1a[r * 192 + 64 + k]) : rna_tf32(W1g[(r - 128) * 192 + 64 + k]);
  } else if (seg == 1) {
    v = (k < 128) ? rna_tf32(W2a[r * 128 + k]) : -rna_tf32(W2g[r * 128 + k - 128]);
  } else if (seg == 2) {
    v = rna_tf32(Wih[r * 65 + k]);
  } else {
    v = rna_tf32(Whh[r * 128 + k]);
  }
  g_wpack[dstoff + ks * R * 8 + r * 8 + p8] = v;
}

// ============================================================================
// k0: v1a/v1g = W1[:, :64] @ x + b1 (fp32 exact)
// ============================================================================
__global__ void k0(const float* __restrict__ x,
                   const float* __restrict__ W1a, const float* __restrict__ b1a,
                   const float* __restrict__ W1g, const float* __restrict__ b1g) {
  __shared__ float xs[64];
  int t = threadIdx.x;
  if (t < 64) xs[t] = x[t];
  __syncthreads();
  const float* W = (t < 128) ? W1a : W1g;
  const float* b = (t < 128) ? b1a : b1g;
  int n = t & 127;
  float s = b[n];
#pragma unroll 8
  for (int k = 0; k < 64; k++) s = fmaf(W[n * 192 + k], xs[k], s);
  g_v1[t] = s;
}

// kdummy: placeholder so ncu's fixed capture index lands on k1.
__global__ void kdummy() {}

// ============================================================================
// mma core: A and B software-pipelined. B row pointers prebuilt by caller;
// RS = per-ks stride in floats (= R*8 for the ks-major image).
// CAT: A = [buf1 | buf2] along K (K8 total chunks, half each).
// ============================================================================
template <int K8, int NT, int RS, bool CAT>
__device__ __forceinline__ void mma_core(
    const float* sm, int abase, int apitch, int abase2,
    const float* const (&wp)[NT],
    int g, int tq, float (&d)[2][NT][4]) {
  uint32_t a[2][4];
  float2 bf[NT];
  {
    const float* apb = sm + abase + g * apitch + tq;
#pragma unroll
    for (int mt = 0; mt < 2; mt++) {
      const float* ap = apb + mt * 16 * apitch;
      a[mt][0] = __float_as_uint(ap[0]);
      a[mt][1] = __float_as_uint(ap[8 * apitch]);
      a[mt][2] = __float_as_uint(ap[4]);
      a[mt][3] = __float_as_uint(ap[8 * apitch + 4]);
    }
#pragma unroll
    for (int nt = 0; nt < NT; nt++) bf[nt] = *(const float2*)(wp[nt]);
  }
#pragma unroll
  for (int ks = 0; ks < K8; ks++) {
    uint32_t an[2][4];
    float2 bn[NT];
    if (ks + 1 < K8) {
      int ab = abase, kk = ks + 1;
      if (CAT) { if (kk >= K8 / 2) { ab = abase2; kk -= K8 / 2; } }
      const float* apb = sm + ab + g * apitch + kk * 8 + tq;
#pragma unroll
      for (int mt = 0; mt < 2; mt++) {
        const float* ap = apb + mt * 16 * apitch;
        an[mt][0] = __float_as_uint(ap[0]);
        an[mt][1] = __float_as_uint(ap[8 * apitch]);
        an[mt][2] = __float_as_uint(ap[4]);
        an[mt][3] = __float_as_uint(ap[8 * apitch + 4]);
      }
#pragma unroll
      for (int nt = 0; nt < NT; nt++)
        bn[nt] = *(const float2*)(wp[nt] + (size_t)(ks + 1) * RS);
    }
#pragma unroll
    for (int nt = 0; nt < NT; nt++) {
      uint32_t b0 = __float_as_uint(bf[nt].x), b1 = __float_as_uint(bf[nt].y);
#pragma unroll
      for (int mt = 0; mt < 2; mt++) mma_tf32(d[mt][nt], a[mt], b0, b1);
    }
    if (ks + 1 < K8) {
#pragma unroll
      for (int nt = 0; nt < NT; nt++) bf[nt] = bn[nt];
#pragma unroll
      for (int mt = 0; mt < 2; mt++)
#pragma unroll
        for (int i = 0; i < 4; i++) a[mt][i] = an[mt][i];
    }
  }
}

template <int NT>
__device__ __forceinline__ void dzero(float (&d)[2][NT][4]) {
#pragma unroll
  for (int mt = 0; mt < 2; mt++)
#pragma unroll
    for (int nt = 0; nt < NT; nt++)
#pragma unroll
      for (int i = 0; i < 4; i++) d[mt][nt][i] = 0.0f;
}

// ============================================================================
// K1: fused engines + tension + GRU. 32 cells/block, 8 warps, 2 CTAs/SM.
// Warp wn = wid (n-split only); every warp covers all 32 cells (mt = 2).
// ============================================================================
__global__ void __launch_bounds__(BT, 2) k1(
    const float* __restrict__ hiddens,
    const float* __restrict__ b2a, const float* __restrict__ b2g,
    const float* __restrict__ bih, const float* __restrict__ bhh) {
  extern __shared__ float sm[];
  const int t = threadIdx.x;
  const int cell0 = blockIdx.x * TC;
  const int lane = t & 31, wn = t >> 5;
  const int g = lane >> 2, tq = lane & 3;

  if (t < 128) sm[OFF_PART + t] = 0.0f;

  // stage h (rna tf32): [32 cells][128] at pitch AP
  const float4* hsrc = (const float4*)(hiddens + (size_t)cell0 * HID);
  for (int i = t; i < TC * 32; i += BT) {
    int c = i >> 5, q = i & 31;
    float4 v = hsrc[i];
    v.x = rna_tf32(v.x); v.y = rna_tf32(v.y); v.z = rna_tf32(v.z); v.w = rna_tf32(v.w);
    *(float4*)&sm[OFF_H + c * AP + 4 * q] = v;
  }

  // ---------------- G1a: [relu_a | relu_g] = relu(H @ [W1a;W1g]^T + v1) ------
  {
    __syncthreads();
    float d[2][4][4]; dzero<4>(d);
    const int nb = wn * 32;                 // n in 0..255
    const float* wp[4];
#pragma unroll
    for (int nt = 0; nt < 4; nt++)
      wp[nt] = g_wpack + PW_W1 + (size_t)(nb + nt * 8 + g) * 8 + 2 * tq;
    mma_core<16, 4, 2048, false>(sm, OFF_H, AP, 0, wp, g, tq, d);
#pragma unroll
    for (int nt = 0; nt < 4; nt++) {
      int n = nb + nt * 8 + 2 * tq;
      int base = (n < 128) ? OFF_B1 : OFF_B2;
      int nc = n & 127;
      float bv0 = g_v1[n], bv1 = g_v1[n + 1];
#pragma unroll
      for (int mt = 0; mt < 2; mt++)
#pragma unroll
        for (int rh = 0; rh < 2; rh++) {
          int c = mt * 16 + g + rh * 8;
          sm[base + c * AP + nc]     = rna_tf32(fmaxf(d[mt][nt][rh * 2] + bv0, 0.0f));
          sm[base + c * AP + nc + 1] = rna_tf32(fmaxf(d[mt][nt][rh * 2 + 1] + bv1, 0.0f));
        }
    }
  }

  // ---------------- G1b: HR = H @ Whh^T (raw, no bias) ----------------------
  {
    __syncthreads();
    float d[2][6][4]; dzero<6>(d);
    const int nb = wn * 48;                 // n in 0..383
    const float* wp[6];
#pragma unroll
    for (int nt = 0; nt < 6; nt++)
      wp[nt] = g_wpack + PW_WHH + (size_t)(nb + nt * 8 + g) * 8 + 2 * tq;
    mma_core<16, 6, 3072, false>(sm, OFF_H, AP, 0, wp, g, tq, d);
#pragma unroll
    for (int nt = 0; nt < 6; nt++) {
      int n = nb + nt * 8 + 2 * tq;
#pragma unroll
      for (int mt = 0; mt < 2; mt++)
#pragma unroll
        for (int rh = 0; rh < 2; rh++) {
          int c = mt * 16 + g + rh * 8;
          *(float2*)&sm[OFF_HR + c * HRP + n] =
              make_float2(d[mt][nt][rh * 2], d[mt][nt][rh * 2 + 1]);
        }
    }
  }

  // ---------------- T3: OUT = [B1|B2] @ [W2a|-W2g]^T + (b2a-b2g) (fp32) ------
  {
    __syncthreads();
    float d[2][1][4]; dzero<1>(d);
    const int nb = wn * 8;                  // n in 0..63
    const float* wp[1];
    wp[0] = g_wpack + PW_W2C + (size_t)(nb + g) * 8 + 2 * tq;
    mma_core<32, 1, 512, true>(sm, OFF_B1, AP, OFF_B2, wp, g, tq, d);
    {
      int n = nb + 2 * tq;
      float bv0 = b2a[n] - b2g[n], bv1 = b2a[n + 1] - b2g[n + 1];
#pragma unroll
      for (int mt = 0; mt < 2; mt++)
#pragma unroll
        for (int rh = 0; rh < 2; rh++) {
          int c = mt * 16 + g + rh * 8;
          sm[OFF_OUT + c * OP + n]     = d[mt][0][rh * 2] + bv0;
          sm[OFF_OUT + c * OP + n + 1] = d[mt][0][rh * 2 + 1] + bv1;
        }
    }
  }
  __syncthreads();

  // ---------------- tension + softmax/pool partials ----------------
  {
    float* outb = sm + OFF_OUT;
    float* esm = sm + OFF_RED;
    float* tsm = sm + OFF_RED + TC;
    if (t < TC) {
      float s = 0.0f;
#pragma unroll
      for (int n = 0; n < OUTD; n++) { float v = outb[t * OP + n]; s = fmaf(v, v, s); }
      float tc = s * (1.0f / OUTD);
      outb[t * OP + 64] = rna_tf32(tc);
      esm[t] = expf(tc);
      tsm[t] = tc;
    }
    __syncthreads();
    if (t < OUTD) {
      float s = 0.0f;
#pragma unroll
      for (int c = 0; c < TC; c++) s = fmaf(esm[c], outb[c * OP + t], s);
      g_peout[blockIdx.x * OUTD + t] = s;
    }
    if (t == 0) {
      float se = 0.0f, st = 0.0f;
#pragma unroll
      for (int c = 0; c < TC; c++) { se += esm[c]; st += tsm[c]; }
      g_pe[blockIdx.x] = se;
      g_pt[blockIdx.x] = st;
    }
    __syncthreads();
    for (int i = t; i < TC * OUTD; i += BT) {
      int c = i >> 6, n = i & 63;
      outb[c * OP + n] = rna_tf32(outb[c * OP + n]);
    }
  }

  // ---------------- T4: i-gates mma (triple-tiled) + full GRU epilogue ------
  // nt = gate*2 + j covers Wih rows gate*128 + wn*16 + j*8 .. +8.
  {
    __syncthreads();
    float d[2][6][4]; dzero<6>(d);
    const int nb16 = wn * 16;               // hidden col group 0..127
    const float* wp[6];
#pragma unroll
    for (int nt = 0; nt < 6; nt++) {
      int row = (nt >> 1) * 128 + nb16 + ((nt & 1) << 3) + g;
      wp[nt] = g_wpack + PW_WIH + (size_t)row * 8 + 2 * tq;
    }
    mma_core<8, 6, 3072, false>(sm, OFF_OUT, OP, 0, wp, g, tq, d);

#pragma unroll
    for (int j = 0; j < 2; j++) {
      int n = nb16 + j * 8 + 2 * tq;        // hidden unit index 0..127
      float bir0 = bih[n],      bir1 = bih[n + 1];
      float biz0 = bih[128 + n], biz1 = bih[128 + n + 1];
      float bin0 = bih[256 + n], bin1 = bih[256 + n + 1];
      float wr0 = g_w64[n],      wr1 = g_w64[n + 1];
      float wz0 = g_w64[128 + n], wz1 = g_w64[128 + n + 1];
      float wn0 = g_w64[256 + n], wn1 = g_w64[256 + n + 1];
      float bhr0 = bhh[n],       bhr1 = bhh[n + 1];
      float bhz0 = bhh[128 + n], bhz1 = bhh[128 + n + 1];
      float bhn0 = bhh[256 + n], bhn1 = bhh[256 + n + 1];
      float p0 = 0.0f, p1 = 0.0f;
#pragma unroll
      for (int mt = 0; mt < 2; mt++)
#pragma unroll
        for (int rh = 0; rh < 2; rh++) {
          int c = mt * 16 + g + rh * 8;
          float tc = sm[OFF_OUT + c * OP + 64];
          float ir0 = d[mt][j][rh * 2]     + bir0 + tc * wr0;
          float ir1 = d[mt][j][rh * 2 + 1] + bir1 + tc * wr1;
          float iz0 = d[mt][2 + j][rh * 2]     + biz0 + tc * wz0;
          float iz1 = d[mt][2 + j][rh * 2 + 1] + biz1 + tc * wz1;
          float in0 = d[mt][4 + j][rh * 2]     + bin0 + tc * wn0;
          float in1 = d[mt][4 + j][rh * 2 + 1] + bin1 + tc * wn1;
          float2 hr = *(const float2*)&sm[OFF_HR + c * HRP + n];
          float2 hz = *(const float2*)&sm[OFF_HR + c * HRP + 128 + n];
          float2 hn = *(const float2*)&sm[OFF_HR + c * HRP + 256 + n];
          float2 h  = *(const float2*)&sm[OFF_H + c * AP + n];
          float r0 = sigmoidf_(ir0 + hr.x + bhr0);
          float r1 = sigmoidf_(ir1 + hr.y + bhr1);
          float z0 = sigmoidf_(iz0 + hz.x + bhz0);
          float z1 = sigmoidf_(iz1 + hz.y + bhz1);
          float nv0 = tanhf_(in0 + r0 * (hn.x + bhn0));
          float nv1 = tanhf_(in1 + r1 * (hn.y + bhn1));
          float nh0 = (1.0f - z0) * nv0 + z0 * h.x;
          float nh1 = (1.0f - z1) * nv1 + z1 * h.y;
          *(float2*)(g_newh + (size_t)(cell0 + c) * HID + n) = make_float2(nh0, nh1);
          p0 += nh0; p1 += nh1;
        }
      atomicAdd(&sm[OFF_PART + n], p0);
      atomicAdd(&sm[OFF_PART + n + 1], p1);
    }
  }
  __syncthreads();
  if (t < 128) g_pfm[blockIdx.x * HID + t] = sm[OFF_PART + t];
}

// ============================================================================
// K2a: faction means (parallel, coalesced). 512 blocks per faction.
// ============================================================================
__global__ void __launch_bounds__(128) k2a() {
  int f = blockIdx.x, d = threadIdx.x;
  const float* p = g_pfm + (size_t)f * 512 * HID + d;
  float s = 0.0f;
#pragma unroll 16
  for (int b = 0; b < 512; b++) s += p[b * HID];
  g_fm[f * HID + d] = s * (1.0f / 16384.0f);
}

// ============================================================================
// K2p: parallel 1st-level reduction of g_peout (4096 blocks -> 64 partials)
// Block j sums blocks [j*64, (j+1)*64); loads fully coalesced across o.
// ============================================================================
__global__ void __launch_bounds__(64) k2p() {
  int j = blockIdx.x, o = threadIdx.x;
  const float* p = g_peout + (size_t)j * 64 * OUTD + o;
  float s = 0.0f;
#pragma unroll 16
  for (int b = 0; b < 64; b++) s += p[b * OUTD];
  g_pout2[j * OUTD + o] = s;
}

// ============================================================================
// K2b: global opinion, scalar reductions, pooled head
// ============================================================================
__global__ void __launch_bounds__(256) k2b(const float* __restrict__ Wo,
                                           const float* __restrict__ bo,
                                           float* __restrict__ d_out) {
  __shared__ float red[256];
  __shared__ float comb[64];
  __shared__ float sume_s;
  int t = threadIdx.x;

  if (t < HID) {
    float s = 0.0f;
#pragma unroll
    for (int f = 0; f < 8; f++) s += g_fm[f * HID + t];
    g_go[t] = s * 0.125f;
  }

  float se = 0.0f, st = 0.0f;
  for (int b = t; b < NBLK; b += 256) { se += g_pe[b]; st += g_pt[b]; }
  red[t] = se;
  __syncthreads();
  for (int s2 = 128; s2 > 0; s2 >>= 1) { if (t < s2) red[t] += red[t + s2]; __syncthreads(); }
  if (t == 0) sume_s = red[0];
  __syncthreads();
  red[t] = st;
  __syncthreads();
  for (int s2 = 128; s2 > 0; s2 >>= 1) { if (t < s2) red[t] += red[t + s2]; __syncthreads(); }
  if (t == 0) d_out[64] = red[0] * (1.0f / NCELLS);

  if (t < 64) {
    float s = 0.0f;
#pragma unroll 16
    for (int j = 0; j < 64; j++) s += g_pout2[j * OUTD + t];
    comb[t] = s / sume_s;
  }
  __syncthreads();
  if (t < 64) {
    float s = bo[t];
#pragma unroll
    for (int d = 0; d < 64; d++) s = fmaf(Wo[t * 64 + d], comb[d], s);
    d_out[t] = s;
  }
}

// ============================================================================
// K3: apply faction sync + debate, stream to output
// ============================================================================
__global__ void __launch_bounds__(256) k3(const int* __restrict__ step,
                                          float* __restrict__ d_out) {
  int i = blockIdx.x * 256 + threadIdx.x;
  float4 nh = ((const float4*)g_newh)[i];
  int c = i >> 5;
  int dq = i & 31;
  int f = c >> 14;
  float4 fm4 = ((const float4*)g_fm)[f * 32 + dq];
  float4 v;
  v.x = 0.85f * nh.x + 0.15f * fm4.x;
  v.y = 0.85f * nh.y + 0.15f * fm4.y;
  v.z = 0.85f * nh.z + 0.15f * fm4.z;
  v.w = 0.85f * nh.w + 0.15f * fm4.w;
  if (((c & 16383) < 4096) && (*step > 5)) {
    float4 go4 = ((const float4*)g_go)[dq];
    v.x = 0.85f * v.x + 0.15f * go4.x;
    v.y = 0.85f * v.y + 0.15f * go4.y;
    v.z = 0.85f * v.z + 0.15f * go4.z;
    v.w = 0.85f * v.w + 0.15f * go4.w;
  }
  float* o = d_out + 65 + (size_t)i * 4;
  o[0] = v.x; o[1] = v.y; o[2] = v.z; o[3] = v.w;
}

extern "C" void kernel_launch(void* const* d_in, const int* in_sizes, int n_in,
                              void* d_out, int out_size) {
  const float* x    = (const float*)d_in[0];
  const float* hid  = (const float*)d_in[1];
  const float* W1a  = (const float*)d_in[2];
  const float* b1a  = (const float*)d_in[3];
  const float* W2a  = (const float*)d_in[4];
  const float* b2a  = (const float*)d_in[5];
  const float* W1g  = (const float*)d_in[6];
  const float* b1g  = (const float*)d_in[7];
  const float* W2g  = (const float*)d_in[8];
  const float* b2g  = (const float*)d_in[9];
  const float* Wih  = (const float*)d_in[10];
  const float* Whh  = (const float*)d_in[11];
  const float* bih  = (const float*)d_in[12];
  const float* bhh  = (const float*)d_in[13];
  const float* Wo   = (const float*)d_in[14];
  const float* bo   = (const float*)d_in[15];
  const int* step   = (const int*)d_in[16];
  float* out = (float*)d_out;

  cudaFuncSetAttribute(k1, cudaFuncAttributeMaxDynamicSharedMemorySize, SMEM_BYTES);

  kprep<<<dim3(192, 5), 256>>>(W1a, W2a, W1g, W2g, Wih, Whh);      // launch 0
  k0<<<1, 256>>>(x, W1a, b1a, W1g, b1g);                           // launch 1
  kdummy<<<1, 32>>>();                                             // launch 2 (capture pad)
  k1<<<NBLK, BT, SMEM_BYTES>>>(hid, b2a, b2g, bih, bhh);           // launch 3 <- ncu
  k2a<<<8, 128>>>();                                               // launch 4
  k2p<<<64, 64>>>();                                               // launch 5
  k2b<<<1, 256>>>(Wo, bo, out);                                    // launch 6
  k3<<<(NCELLS * HID / 4) / 256, 256>>>(step, out);                // launch 7
}

// round 15
// speedup vs baseline: 1.3196x; 1.1176x over previous
#include <cuda_runtime.h>
#include <math.h>
#include <stdint.h>

#define NCELLS 131072
#define HID 128
#define OUTD 64
#define TC 32                 // cells per block
#define NBLK (NCELLS / TC)    // 4096
#define BT 256                // threads per block (8 warps)

#define AP 132                // pitch for H/B1/B2 (mod 32 == 4 -> conflict-free)
#define HRP 388               // pitch for HR raw buffer (mod 32 == 4)
#define OP 68                 // pitch for OUT

// ---- dynamic smem layout (float offsets) ----
#define OFF_H    0                        // [32][AP]
#define OFF_B1   (OFF_H + TC * AP)        // [32][AP] relu_a
#define OFF_B2   (OFF_B1 + TC * AP)       // [32][AP] relu_g
#define OFF_HR   (OFF_B2 + TC * AP)       // [32][HRP] raw hr|hz|hn (no bias)
#define OFF_OUT  (OFF_HR + TC * HRP)      // [32][OP], col 64 = rna(t)
#define OFF_PART (OFF_OUT + TC * OP)      // [128] faction partials
#define OFF_RED  (OFF_PART + 128)         // esm[32], tsm[32]
#define SMEM_FLOATS (OFF_RED + 64)
#define SMEM_BYTES (SMEM_FLOATS * 4)

// ---- packed weight image (ks-major: [ks][row][8] per matrix) ----
#define PW_W1  0              // R=256, K=128  ([W1a;W1g] hidden part)
#define PW_W2C 32768          // R=64,  K=256  ([W2a | -W2g])
#define PW_WIH 49152          // R=384, K=64   (rows: ir, iz, i_n)
#define PW_WHH 73728          // R=384, K=128  (rows: hr, hz, hn)
#define WPACK_FLOATS 122880

// ---- scratch (device globals) ----
__device__ float g_wpack[WPACK_FLOATS];
__device__ float g_w64[384];                 // Wih[:,64] (t column)
__device__ float g_newh[NCELLS * HID];
__device__ float g_pfm[NBLK * HID];
__device__ float g_fma[64 * HID];            // 1st-level faction partials
__device__ float g_peout[NBLK * OUTD];
__device__ float g_pout2[64 * 64];           // 2nd-level peout partials
__device__ float g_pe[NBLK];
__device__ float g_pt[NBLK];
__device__ float g_v1[256];                  // W1[:, :64]@x + b1 (a then g)
__device__ float g_fm[8 * HID];
__device__ float g_go[HID];

__device__ __forceinline__ float sigmoidf_(float v) {
  return 1.0f / (1.0f + __expf(-v));
}
__device__ __forceinline__ float tanhf_(float v) {
  return 2.0f / (1.0f + __expf(-2.0f * v)) - 1.0f;
}

__device__ __forceinline__ float rna_tf32(float x) {
  uint32_t u;
  asm("cvt.rna.tf32.f32 %0, %1;" : "=r"(u) : "f"(x));
  return __uint_as_float(u);
}

__device__ __forceinline__ void mma_tf32(float* d, const uint32_t* a, uint32_t b0, uint32_t b1) {
  asm volatile(
      "mma.sync.aligned.m16n8k8.row.col.f32.tf32.tf32.f32 "
      "{%0,%1,%2,%3}, {%4,%5,%6,%7}, {%8,%9}, {%0,%1,%2,%3};\n"
      : "+f"(d[0]), "+f"(d[1]), "+f"(d[2]), "+f"(d[3])
      : "r"(a[0]), "r"(a[1]), "r"(a[2]), "r"(a[3]), "r"(b0), "r"(b1));
}

// ============================================================================
// kprep: rna-convert + permute weights into ks-major fragment image.
// (r, k): ks = k/8, q = k%8 -> dst = ks*R*8 + r*8 + p, p = 2q (q<4) else 2(q-4)+1.
// ============================================================================
__global__ void kprep(const float* __restrict__ W1a, const float* __restrict__ W2a,
                      const float* __restrict__ W1g, const float* __restrict__ W2g,
                      const float* __restrict__ Wih, const float* __restrict__ Whh) {
  int seg = blockIdx.y;
  int e = blockIdx.x * 256 + threadIdx.x;
  int R, K, dstoff;
  if (seg == 0)      { R = 256; K = 128; dstoff = PW_W1; }
  else if (seg == 1) { R = 64;  K = 256; dstoff = PW_W2C; }
  else if (seg == 2) { R = 384; K = 64;  dstoff = PW_WIH; }
  else if (seg == 3) { R = 384; K = 128; dstoff = PW_WHH; }
  else {             // Wih col 64
    if (e < 384) g_w64[e] = rna_tf32(Wih[e * 65 + 64]);
    return;
  }
  if (e >= R * K) return;
  int r = e / K, pcol = e - r * K;
  int ks = pcol >> 3, p8 = pcol & 7;
  int k = ks * 8 + (p8 >> 1) + ((p8 & 1) << 2);
  float v;
  if (seg == 0) {
    v = (r < 128) ? rna_tf32(W1a[r * 192 + 64 + k]) : rna_tf32(W1g[(r - 128) * 192 + 64 + k]);
  } else if (seg == 1) {
    v = (k < 128) ? rna_tf32(W2a[r * 128 + k]) : -rna_tf32(W2g[r * 128 + k - 128]);
  } else if (seg == 2) {
    v = rna_tf32(Wih[r * 65 + k]);
  } else {
    v = rna_tf32(Whh[r * 128 + k]);
  }
  g_wpack[dstoff + ks * R * 8 + r * 8 + p8] = v;
}

// ============================================================================
// k0: v1a/v1g = W1[:, :64] @ x + b1 (fp32 exact)
// ============================================================================
__global__ void k0(const float* __restrict__ x,
                   const float* __restrict__ W1a, const float* __restrict__ b1a,
                   const float* __restrict__ W1g, const float* __restrict__ b1g) {
  __shared__ float xs[64];
  int t = threadIdx.x;
  if (t < 64) xs[t] = x[t];
  __syncthreads();
  const float* W = (t < 128) ? W1a : W1g;
  const float* b = (t < 128) ? b1a : b1g;
  int n = t & 127;
  float s = b[n];
#pragma unroll 8
  for (int k = 0; k < 64; k++) s = fmaf(W[n * 192 + k], xs[k], s);
  g_v1[t] = s;
}

// kdummy: placeholder so ncu's fixed capture index lands on k1.
__global__ void kdummy() {}

// ============================================================================
// mma core: A and B software-pipelined; first B fragments (bf0) preloaded by
// the caller BEFORE the stage barrier (hides stage-start L2 latency).
// RS = per-ks stride in floats (= R*8 for the ks-major image).
// CAT: A = [buf1 | buf2] along K (K8 total chunks, half each).
// ============================================================================
template <int K8, int NT, int RS, bool CAT>
__device__ __forceinline__ void mma_core(
    const float* sm, int abase, int apitch, int abase2,
    const float* const (&wp)[NT], const float2 (&bf0)[NT],
    int g, int tq, float (&d)[2][NT][4]) {
  uint32_t a[2][4];
  float2 bf[NT];
#pragma unroll
  for (int nt = 0; nt < NT; nt++) bf[nt] = bf0[nt];
  {
    const float* apb = sm + abase + g * apitch + tq;
#pragma unroll
    for (int mt = 0; mt < 2; mt++) {
      const float* ap = apb + mt * 16 * apitch;
      a[mt][0] = __float_as_uint(ap[0]);
      a[mt][1] = __float_as_uint(ap[8 * apitch]);
      a[mt][2] = __float_as_uint(ap[4]);
      a[mt][3] = __float_as_uint(ap[8 * apitch + 4]);
    }
  }
#pragma unroll
  for (int ks = 0; ks < K8; ks++) {
    uint32_t an[2][4];
    float2 bn[NT];
    if (ks + 1 < K8) {
      int ab = abase, kk = ks + 1;
      if (CAT) { if (kk >= K8 / 2) { ab = abase2; kk -= K8 / 2; } }
      const float* apb = sm + ab + g * apitch + kk * 8 + tq;
#pragma unroll
      for (int mt = 0; mt < 2; mt++) {
        const float* ap = apb + mt * 16 * apitch;
        an[mt][0] = __float_as_uint(ap[0]);
        an[mt][1] = __float_as_uint(ap[8 * apitch]);
        an[mt][2] = __float_as_uint(ap[4]);
        an[mt][3] = __float_as_uint(ap[8 * apitch + 4]);
      }
#pragma unroll
      for (int nt = 0; nt < NT; nt++)
        bn[nt] = *(const float2*)(wp[nt] + (size_t)(ks + 1) * RS);
    }
#pragma unroll
    for (int nt = 0; nt < NT; nt++) {
      uint32_t b0 = __float_as_uint(bf[nt].x), b1 = __float_as_uint(bf[nt].y);
#pragma unroll
      for (int mt = 0; mt < 2; mt++) mma_tf32(d[mt][nt], a[mt], b0, b1);
    }
    if (ks + 1 < K8) {
#pragma unroll
      for (int nt = 0; nt < NT; nt++) bf[nt] = bn[nt];
#pragma unroll
      for (int mt = 0; mt < 2; mt++)
#pragma unroll
        for (int i = 0; i < 4; i++) a[mt][i] = an[mt][i];
    }
  }
}

template <int NT>
__device__ __forceinline__ void dzero(float (&d)[2][NT][4]) {
#pragma unroll
  for (int mt = 0; mt < 2; mt++)
#pragma unroll
    for (int nt = 0; nt < NT; nt++)
#pragma unroll
      for (int i = 0; i < 4; i++) d[mt][nt][i] = 0.0f;
}

// ============================================================================
// K1: fused engines + tension + GRU. 32 cells/block, 8 warps, 2 CTAs/SM.
// Warp wn = wid (n-split only); every warp covers all 32 cells (mt = 2).
// ============================================================================
__global__ void __launch_bounds__(BT, 2) k1(
    const float* __restrict__ hiddens,
    const float* __restrict__ b2a, const float* __restrict__ b2g,
    const float* __restrict__ bih, const float* __restrict__ bhh) {
  extern __shared__ float sm[];
  const int t = threadIdx.x;
  const int cell0 = blockIdx.x * TC;
  const int lane = t & 31, wn = t >> 5;
  const int g = lane >> 2, tq = lane & 3;

  if (t < 128) sm[OFF_PART + t] = 0.0f;

  // G1a B pointers + first fragments (independent of smem -> issue early)
  const float* wpA[4];
  float2 bfA[4];
#pragma unroll
  for (int nt = 0; nt < 4; nt++) {
    wpA[nt] = g_wpack + PW_W1 + (size_t)(wn * 32 + nt * 8 + g) * 8 + 2 * tq;
    bfA[nt] = *(const float2*)(wpA[nt]);
  }

  // stage h (rna tf32): [32 cells][128] at pitch AP
  const float4* hsrc = (const float4*)(hiddens + (size_t)cell0 * HID);
  for (int i = t; i < TC * 32; i += BT) {
    int c = i >> 5, q = i & 31;
    float4 v = hsrc[i];
    v.x = rna_tf32(v.x); v.y = rna_tf32(v.y); v.z = rna_tf32(v.z); v.w = rna_tf32(v.w);
    *(float4*)&sm[OFF_H + c * AP + 4 * q] = v;
  }

  // ---------------- G1a: [relu_a | relu_g] = relu(H @ [W1a;W1g]^T + v1) ------
  const float* wpB[6];
  float2 bfB[6];
  {
    __syncthreads();
    float d[2][4][4]; dzero<4>(d);
    const int nb = wn * 32;                 // n in 0..255
    mma_core<16, 4, 2048, false>(sm, OFF_H, AP, 0, wpA, bfA, g, tq, d);
    // prefetch G1b first B fragments (hides L2 latency behind epilogue+barrier)
#pragma unroll
    for (int nt = 0; nt < 6; nt++) {
      wpB[nt] = g_wpack + PW_WHH + (size_t)(wn * 48 + nt * 8 + g) * 8 + 2 * tq;
      bfB[nt] = *(const float2*)(wpB[nt]);
    }
#pragma unroll
    for (int nt = 0; nt < 4; nt++) {
      int n = nb + nt * 8 + 2 * tq;
      int base = (n < 128) ? OFF_B1 : OFF_B2;
      int nc = n & 127;
      float bv0 = g_v1[n], bv1 = g_v1[n + 1];
#pragma unroll
      for (int mt = 0; mt < 2; mt++)
#pragma unroll
        for (int rh = 0; rh < 2; rh++) {
          int c = mt * 16 + g + rh * 8;
          sm[base + c * AP + nc]     = rna_tf32(fmaxf(d[mt][nt][rh * 2] + bv0, 0.0f));
          sm[base + c * AP + nc + 1] = rna_tf32(fmaxf(d[mt][nt][rh * 2 + 1] + bv1, 0.0f));
        }
    }
  }

  // ---------------- G1b: HR = H @ Whh^T (raw, no bias) ----------------------
  const float* wpC[1];
  float2 bfC[1];
  {
    __syncthreads();
    float d[2][6][4]; dzero<6>(d);
    const int nb = wn * 48;                 // n in 0..383
    mma_core<16, 6, 3072, false>(sm, OFF_H, AP, 0, wpB, bfB, g, tq, d);
    // prefetch T3 first B fragment
    wpC[0] = g_wpack + PW_W2C + (size_t)(wn * 8 + g) * 8 + 2 * tq;
    bfC[0] = *(const float2*)(wpC[0]);
#pragma unroll
    for (int nt = 0; nt < 6; nt++) {
      int n = nb + nt * 8 + 2 * tq;
#pragma unroll
      for (int mt = 0; mt < 2; mt++)
#pragma unroll
        for (int rh = 0; rh < 2; rh++) {
          int c = mt * 16 + g + rh * 8;
          *(float2*)&sm[OFF_HR + c * HRP + n] =
              make_float2(d[mt][nt][rh * 2], d[mt][nt][rh * 2 + 1]);
        }
    }
  }

  // ---------------- T3: OUT = [B1|B2] @ [W2a|-W2g]^T + (b2a-b2g) (fp32) ------
  {
    __syncthreads();
    float d[2][1][4]; dzero<1>(d);
    const int nb = wn * 8;                  // n in 0..63
    mma_core<32, 1, 512, true>(sm, OFF_B1, AP, OFF_B2, wpC, bfC, g, tq, d);
    {
      int n = nb + 2 * tq;
      float bv0 = b2a[n] - b2g[n], bv1 = b2a[n + 1] - b2g[n + 1];
#pragma unroll
      for (int mt = 0; mt < 2; mt++)
#pragma unroll
        for (int rh = 0; rh < 2; rh++) {
          int c = mt * 16 + g + rh * 8;
          sm[OFF_OUT + c * OP + n]     = d[mt][0][rh * 2] + bv0;
          sm[OFF_OUT + c * OP + n + 1] = d[mt][0][rh * 2 + 1] + bv1;
        }
    }
  }
  __syncthreads();

  // ---------------- tension + softmax/pool partials ----------------
  const float* wpD[6];
  float2 bfD[6];
  {
    float* outb = sm + OFF_OUT;
    float* esm = sm + OFF_RED;
    float* tsm = sm + OFF_RED + TC;
    if (t < TC) {
      float s = 0.0f;
#pragma unroll
      for (int n = 0; n < OUTD; n++) { float v = outb[t * OP + n]; s = fmaf(v, v, s); }
      float tc = s * (1.0f / OUTD);
      outb[t * OP + 64] = rna_tf32(tc);
      esm[t] = expf(tc);
      tsm[t] = tc;
    }
    __syncthreads();
    if (t < OUTD) {
      float s = 0.0f;
#pragma unroll
      for (int c = 0; c < TC; c++) s = fmaf(esm[c], outb[c * OP + t], s);
      g_peout[blockIdx.x * OUTD + t] = s;
    }
    if (wn == 2) {            // warp-shuffle reduction of esm (warps 0/1 pool)
      float v = esm[lane];
#pragma unroll
      for (int m = 16; m; m >>= 1) v += __shfl_xor_sync(0xffffffffu, v, m);
      if (lane == 0) g_pe[blockIdx.x] = v;
    } else if (wn == 3) {     // tsm
      float v = tsm[lane];
#pragma unroll
      for (int m = 16; m; m >>= 1) v += __shfl_xor_sync(0xffffffffu, v, m);
      if (lane == 0) g_pt[blockIdx.x] = v;
    }
    __syncthreads();
    // prefetch T4 first B fragments during the rna pass
#pragma unroll
    for (int nt = 0; nt < 6; nt++) {
      int row = (nt >> 1) * 128 + wn * 16 + ((nt & 1) << 3) + g;
      wpD[nt] = g_wpack + PW_WIH + (size_t)row * 8 + 2 * tq;
      bfD[nt] = *(const float2*)(wpD[nt]);
    }
    for (int i = t; i < TC * OUTD; i += BT) {
      int c = i >> 6, n = i & 63;
      outb[c * OP + n] = rna_tf32(outb[c * OP + n]);
    }
  }

  // ---------------- T4: i-gates mma (triple-tiled) + full GRU epilogue ------
  // nt = gate*2 + j covers Wih rows gate*128 + wn*16 + j*8 .. +8.
  {
    __syncthreads();
    float d[2][6][4]; dzero<6>(d);
    const int nb16 = wn * 16;               // hidden col group 0..127
    mma_core<8, 6, 3072, false>(sm, OFF_OUT, OP, 0, wpD, bfD, g, tq, d);

#pragma unroll
    for (int j = 0; j < 2; j++) {
      int n = nb16 + j * 8 + 2 * tq;        // hidden unit index 0..127
      float bir0 = bih[n],      bir1 = bih[n + 1];
      float biz0 = bih[128 + n], biz1 = bih[128 + n + 1];
      float bin0 = bih[256 + n], bin1 = bih[256 + n + 1];
      float wr0 = g_w64[n],      wr1 = g_w64[n + 1];
      float wz0 = g_w64[128 + n], wz1 = g_w64[128 + n + 1];
      float wn0 = g_w64[256 + n], wn1 = g_w64[256 + n + 1];
      float bhr0 = bhh[n],       bhr1 = bhh[n + 1];
      float bhz0 = bhh[128 + n], bhz1 = bhh[128 + n + 1];
      float bhn0 = bhh[256 + n], bhn1 = bhh[256 + n + 1];
      float p0 = 0.0f, p1 = 0.0f;
#pragma unroll
      for (int mt = 0; mt < 2; mt++)
#pragma unroll
        for (int rh = 0; rh < 2; rh++) {
          int c = mt * 16 + g + rh * 8;
          float tc = sm[OFF_OUT + c * OP + 64];
          float ir0 = d[mt][j][rh * 2]     + bir0 + tc * wr0;
          float ir1 = d[mt][j][rh * 2 + 1] + bir1 + tc * wr1;
          float iz0 = d[mt][2 + j][rh * 2]     + biz0 + tc * wz0;
          float iz1 = d[mt][2 + j][rh * 2 + 1] + biz1 + tc * wz1;
          float in0 = d[mt][4 + j][rh * 2]     + bin0 + tc * wn0;
          float in1 = d[mt][4 + j][rh * 2 + 1] + bin1 + tc * wn1;
          float2 hr = *(const float2*)&sm[OFF_HR + c * HRP + n];
          float2 hz = *(const float2*)&sm[OFF_HR + c * HRP + 128 + n];
          float2 hn = *(const float2*)&sm[OFF_HR + c * HRP + 256 + n];
          float2 h  = *(const float2*)&sm[OFF_H + c * AP + n];
          float r0 = sigmoidf_(ir0 + hr.x + bhr0);
          float r1 = sigmoidf_(ir1 + hr.y + bhr1);
          float z0 = sigmoidf_(iz0 + hz.x + bhz0);
          float z1 = sigmoidf_(iz1 + hz.y + bhz1);
          float nv0 = tanhf_(in0 + r0 * (hn.x + bhn0));
          float nv1 = tanhf_(in1 + r1 * (hn.y + bhn1));
          float nh0 = (1.0f - z0) * nv0 + z0 * h.x;
          float nh1 = (1.0f - z1) * nv1 + z1 * h.y;
          *(float2*)(g_newh + (size_t)(cell0 + c) * HID + n) = make_float2(nh0, nh1);
          p0 += nh0; p1 += nh1;
        }
      // reduce over g (lanes 4 apart) before touching smem atomics
#pragma unroll
      for (int m = 4; m <= 16; m <<= 1) {
        p0 += __shfl_xor_sync(0xffffffffu, p0, m);
        p1 += __shfl_xor_sync(0xffffffffu, p1, m);
      }
      if (lane < 4) {
        atomicAdd(&sm[OFF_PART + n], p0);
        atomicAdd(&sm[OFF_PART + n + 1], p1);
      }
    }
  }
  __syncthreads();
  if (t < 128) g_pfm[blockIdx.x * HID + t] = sm[OFF_PART + t];
}

// ============================================================================
// K2a: 1st-level faction partials: 64 blocks, each sums 64 pfm blocks.
// ============================================================================
__global__ void __launch_bounds__(128) k2a() {
  int b = blockIdx.x, d = threadIdx.x;
  const float* p = g_pfm + (size_t)b * 64 * HID + d;
  float s = 0.0f;
#pragma unroll 16
  for (int i = 0; i < 64; i++) s += p[i * HID];
  g_fma[b * HID + d] = s;
}

// ============================================================================
// K2p: parallel 1st-level reduction of g_peout (4096 blocks -> 64 partials)
// ============================================================================
__global__ void __launch_bounds__(64) k2p() {
  int j = blockIdx.x, o = threadIdx.x;
  const float* p = g_peout + (size_t)j * 64 * OUTD + o;
  float s = 0.0f;
#pragma unroll 16
  for (int b = 0; b < 64; b++) s += p[b * OUTD];
  g_pout2[j * OUTD + o] = s;
}

// ============================================================================
// K2b: faction means, global opinion, scalar reductions, pooled head
// ============================================================================
__global__ void __launch_bounds__(256) k2b(const float* __restrict__ Wo,
                                           const float* __restrict__ bo,
                                           float* __restrict__ d_out) {
  __shared__ float red[256];
  __shared__ float comb[64];
  __shared__ float sume_s;
  int t = threadIdx.x;

  if (t < HID) {
    float go = 0.0f;
#pragma unroll
    for (int f = 0; f < 8; f++) {
      float s = 0.0f;
#pragma unroll
      for (int j = 0; j < 8; j++) s += g_fma[(f * 8 + j) * HID + t];
      s *= (1.0f / 16384.0f);
      g_fm[f * HID + t] = s;
      go += s;
    }
    g_go[t] = go * 0.125f;
  }

  float se = 0.0f, st = 0.0f;
  for (int b = t; b < NBLK; b += 256) { se += g_pe[b]; st += g_pt[b]; }
  red[t] = se;
  __syncthreads();
  for (int s2 = 128; s2 > 0; s2 >>= 1) { if (t < s2) red[t] += red[t + s2]; __syncthreads(); }
  if (t == 0) sume_s = red[0];
  __syncthreads();
  red[t] = st;
  __syncthreads();
  for (int s2 = 128; s2 > 0; s2 >>= 1) { if (t < s2) red[t] += red[t + s2]; __syncthreads(); }
  if (t == 0) d_out[64] = red[0] * (1.0f / NCELLS);

  if (t < 64) {
    float s = 0.0f;
#pragma unroll 16
    for (int j = 0; j < 64; j++) s += g_pout2[j * OUTD + t];
    comb[t] = s / sume_s;
  }
  __syncthreads();
  if (t < 64) {
    float s = bo[t];
#pragma unroll
    for (int d = 0; d < 64; d++) s = fmaf(Wo[t * 64 + d], comb[d], s);
    d_out[t] = s;
  }
}

// ============================================================================
// K3: apply faction sync + debate, stream to output
// ============================================================================
__global__ void __launch_bounds__(256) k3(const int* __restrict__ step,
                                          float* __restrict__ d_out) {
  int i = blockIdx.x * 256 + threadIdx.x;
  float4 nh = ((const float4*)g_newh)[i];
  int c = i >> 5;
  int dq = i & 31;
  int f = c >> 14;
  float4 fm4 = ((const float4*)g_fm)[f * 32 + dq];
  float4 v;
  v.x = 0.85f * nh.x + 0.15f * fm4.x;
  v.y = 0.85f * nh.y + 0.15f * fm4.y;
  v.z = 0.85f * nh.z + 0.15f * fm4.z;
  v.w = 0.85f * nh.w + 0.15f * fm4.w;
  if (((c & 16383) < 4096) && (*step > 5)) {
    float4 go4 = ((const float4*)g_go)[dq];
    v.x = 0.85f * v.x + 0.15f * go4.x;
    v.y = 0.85f * v.y + 0.15f * go4.y;
    v.z = 0.85f * v.z + 0.15f * go4.z;
    v.w = 0.85f * v.w + 0.15f * go4.w;
  }
  float* o = d_out + 65 + (size_t)i * 4;
  o[0] = v.x; o[1] = v.y; o[2] = v.z; o[3] = v.w;
}

extern "C" void kernel_launch(void* const* d_in, const int* in_sizes, int n_in,
                              void* d_out, int out_size) {
  const float* x    = (const float*)d_in[0];
  const float* hid  = (const float*)d_in[1];
  const float* W1a  = (const float*)d_in[2];
  const float* b1a  = (const float*)d_in[3];
  const float* W2a  = (const float*)d_in[4];
  const float* b2a  = (const float*)d_in[5];
  const float* W1g  = (const float*)d_in[6];
  const float* b1g  = (const float*)d_in[7];
  const float* W2g  = (const float*)d_in[8];
  const float* b2g  = (const float*)d_in[9];
  const float* Wih  = (const float*)d_in[10];
  const float* Whh  = (const float*)d_in[11];
  const float* bih  = (const float*)d_in[12];
  const float* bhh  = (const float*)d_in[13];
  const float* Wo   = (const float*)d_in[14];
  const float* bo   = (const float*)d_in[15];
  const int* step   = (const int*)d_in[16];
  float* out = (float*)d_out;

  cudaFuncSetAttribute(k1, cudaFuncAttributeMaxDynamicSharedMemorySize, SMEM_BYTES);

  kprep<<<dim3(192, 5), 256>>>(W1a, W2a, W1g, W2g, Wih, Whh);      // launch 0
  k0<<<1, 256>>>(x, W1a, b1a, W1g, b1g);                           // launch 1
  kdummy<<<1, 32>>>();                                             // launch 2 (capture pad)
  k1<<<NBLK, BT, SMEM_BYTES>>>(hid, b2a, b2g, bih, bhh);           // launch 3 <- ncu
  k2a<<<64, 128>>>();                                              // launch 4
  k2p<<<64, 64>>>();                                               // launch 5
  k2b<<<1, 256>>>(Wo, bo, out);                                    // launch 6
  k3<<<(NCELLS * HID / 4) / 256, 256>>>(step, out);                // launch 7
}